// round 15
// baseline (speedup 1.0000x reference)
#include <cuda_runtime.h>

// Problem constants (fixed by the dataset)
#define NN 64
#define PP 17
#define HH 192
#define WW 192
#define NP (NN * PP)            // 1088 items == 34 blocks * 32 threads exactly

// ln(2) folded into stencil coefficients (log2-domain math):
#define C_HALF_LN2    0.34657359f
#define C_QUARTER_LN2 0.17328680f

__global__ __launch_bounds__(32)
void taylor_kernel(const float2* __restrict__ coords,
                   const float*  __restrict__ hm,
                   float2*       __restrict__ out)
{
    // thread-per-item, exact fit: 34 * 32 == 1088, no bounds check.
    // One warp per block spread across 34 SMs: minimal per-SM L1tex
    // queueing for the divergent 13-tap gathers.
    int i = blockIdx.x * 32 + threadIdx.x;

    float2 c = coords[i];                        // (cx, cy) normalized
    float xf = c.x * (float)WW;
    float yf = c.y * (float)HH;

    int px = (int)xf;                            // trunc == floor (coords >= 0)
    int py = (int)yf;

    bool inb = (px > 1) && (px < WW - 2) && (py > 1) && (py < HH - 2);

    int pxc = min(max(px, 2), WW - 3);
    int pyc = min(max(py, 2), HH - 3);

    // 32-bit base offset: max index < 2^26, so the coords->gather dependent
    // chain has no 64-bit IMAD pairs.
    unsigned base = (unsigned)i * (HH * WW) + (unsigned)pyc * WW + (unsigned)pxc;

    // 13 independent gathers, issued back-to-back (MLP ~13, one memory
    // round trip, overlapped across 1088 threads chip-wide).
    auto ld = [&](int dy, int dx) -> float {
        float v = __ldg(hm + base + dy * WW + dx);
        return (v == 0.0f) ? 1e-10f : v;         // reference's zero substitution
    };

    float v00  = ld( 0,  0);
    float vxp  = ld( 0,  1);
    float vxm  = ld( 0, -1);
    float vyp  = ld( 1,  0);
    float vym  = ld(-1,  0);
    float vx2p = ld( 0,  2);
    float vx2m = ld( 0, -2);
    float vy2p = ld( 2,  0);
    float vy2m = ld(-2,  0);
    float vpp  = ld( 1,  1);
    float vmp  = ld(-1,  1);
    float vpm  = ld( 1, -1);
    float vmm  = ld(-1, -1);

    // Folded logs: every derivative is a linear combination of logs, so use
    // logs of ratios/products -> 5 MUFU.LG2 instead of 13 logs. Operands
    // bounded by [1e-20, 1e20] (values in (0,1] with 1e-10 substitution):
    // safe in f32 and for __fdividef.
    float inv00sq = __fdividef(1.0f, v00 * v00);
    float gdx = C_HALF_LN2    * __log2f(__fdividef(vxp, vxm));
    float gdy = C_HALF_LN2    * __log2f(__fdividef(vyp, vym));
    float dxx = C_QUARTER_LN2 * __log2f(vx2p * vx2m * inv00sq);
    float dxy = C_QUARTER_LN2 * __log2f(__fdividef(vpp * vmm, vmp * vpm));
    float dyy = C_QUARTER_LN2 * __log2f(vy2p * vy2m * inv00sq);

    float det = fmaf(dxx, dyy, -dxy * dxy);
    bool ok = inb && (det != 0.0f);

    // Branchless solve (reference's safe_det pattern): no BSSY/BSYNC.
    // !ok -> mask = 0, safe = 1 -> offsets vanish; no NaN/Inf can form.
    float safe = ok ? det : 1.0f;
    float mask = ok ? 1.0f : 0.0f;
    float inv  = __fdividef(mask, safe);         // 0 when !ok, 1/det when ok
    xf -= fmaf(dyy, gdx, -dxy * gdy) * inv;
    yf -= fmaf(dxx, gdy, -dxy * gdx) * inv;

    float2 o;
    o.x = yf * (1.0f / (float)HH);               // flip=True -> (y, x)
    o.y = xf * (1.0f / (float)WW);
    out[i] = o;
}

extern "C" void kernel_launch(void* const* d_in, const int* in_sizes, int n_in,
                              void* d_out, int out_size)
{
    const float2* coords = (const float2*)d_in[0];
    const float*  hm     = (const float*)d_in[1];
    float2* out          = (float2*)d_out;

    (void)in_sizes; (void)n_in; (void)out_size;

    taylor_kernel<<<NP / 32, 32>>>(coords, hm, out);
}

// round 17
// speedup vs baseline: 1.0488x; 1.0488x over previous
#include <cuda_runtime.h>

// Problem constants (fixed by the dataset)
#define NN 64
#define PP 17
#define HH 192
#define WW 192
#define NP (NN * PP)            // 1088 items == 34 blocks * 32 threads exactly

// ln(2) folded into stencil coefficients (log2-domain math):
#define C_HALF_LN2    0.34657359f
#define C_QUARTER_LN2 0.17328680f

__global__ __launch_bounds__(32)
void taylor_kernel(const float2* __restrict__ coords,
                   const float*  __restrict__ hm,
                   float2*       __restrict__ out)
{
    // thread-per-item, exact fit: 34 * 32 == 1088, no bounds check.
    // One warp per block spread across 34 SMs: minimal per-SM L1tex
    // queueing for the divergent 13-tap gathers.
    int i = blockIdx.x * 32 + threadIdx.x;

    float2 c = coords[i];                        // (cx, cy) normalized
    float xf = c.x * (float)WW;
    float yf = c.y * (float)HH;

    int px = (int)xf;                            // trunc == floor (coords >= 0)
    int py = (int)yf;

    bool inb = (px > 1) && (px < WW - 2) && (py > 1) && (py < HH - 2);

    int pxc = min(max(px, 2), WW - 3);
    int pyc = min(max(py, 2), HH - 3);

    // 32-bit base offset: max index < 2^26, so the coords->gather dependent
    // chain has no 64-bit IMAD pairs.
    unsigned base = (unsigned)i * (HH * WW) + (unsigned)pyc * WW + (unsigned)pxc;

    // 13 independent gathers, issued back-to-back (MLP ~13, one memory
    // round trip, overlapped across 1088 threads chip-wide).
    auto ld = [&](int dy, int dx) -> float {
        float v = __ldg(hm + base + dy * WW + dx);
        return (v == 0.0f) ? 1e-10f : v;         // reference's zero substitution
    };

    float v00  = ld( 0,  0);
    float vxp  = ld( 0,  1);
    float vxm  = ld( 0, -1);
    float vyp  = ld( 1,  0);
    float vym  = ld(-1,  0);
    float vx2p = ld( 0,  2);
    float vx2m = ld( 0, -2);
    float vy2p = ld( 2,  0);
    float vy2m = ld(-2,  0);
    float vpp  = ld( 1,  1);
    float vmp  = ld(-1,  1);
    float vpm  = ld( 1, -1);
    float vmm  = ld(-1, -1);

    // Folded logs: every derivative is a linear combination of logs, so use
    // logs of ratios/products -> 5 MUFU.LG2 instead of 13 logs. Operands
    // bounded by [1e-20, 1e20] (values in (0,1] with 1e-10 substitution):
    // safe in f32 and for __fdividef.
    float inv00sq = __fdividef(1.0f, v00 * v00);
    float gdx = C_HALF_LN2    * __log2f(__fdividef(vxp, vxm));
    float gdy = C_HALF_LN2    * __log2f(__fdividef(vyp, vym));
    float dxx = C_QUARTER_LN2 * __log2f(vx2p * vx2m * inv00sq);
    float dxy = C_QUARTER_LN2 * __log2f(__fdividef(vpp * vmm, vmp * vpm));
    float dyy = C_QUARTER_LN2 * __log2f(vy2p * vy2m * inv00sq);

    float det = fmaf(dxx, dyy, -dxy * dxy);
    bool ok = inb && (det != 0.0f);

    // Branchless solve (reference's safe_det pattern): no BSSY/BSYNC.
    // !ok -> mask = 0, safe = 1 -> offsets vanish; no NaN/Inf can form.
    float safe = ok ? det : 1.0f;
    float mask = ok ? 1.0f : 0.0f;
    float inv  = __fdividef(mask, safe);         // 0 when !ok, 1/det when ok
    xf -= fmaf(dyy, gdx, -dxy * gdy) * inv;
    yf -= fmaf(dxx, gdy, -dxy * gdx) * inv;

    float2 o;
    o.x = yf * (1.0f / (float)HH);               // flip=True -> (y, x)
    o.y = xf * (1.0f / (float)WW);
    out[i] = o;
}

extern "C" void kernel_launch(void* const* d_in, const int* in_sizes, int n_in,
                              void* d_out, int out_size)
{
    const float2* coords = (const float2*)d_in[0];
    const float*  hm     = (const float*)d_in[1];
    float2* out          = (float2*)d_out;

    (void)in_sizes; (void)n_in; (void)out_size;

    taylor_kernel<<<NP / 32, 32>>>(coords, hm, out);
}